// round 11
// baseline (speedup 1.0000x reference)
#include <cuda_runtime.h>
#include <cstdint>
#include <cstddef>

#define NROWS 8192
#define DDIM  1024
#define CDIM  1000
#define NPROJ 4096   // skip|q|k|v packed
#define NTILE 512    // cluster N-tile
#define QKTILES (NROWS / NTILE)   // 16 col-tiles in QK
#define KSPLIT_AV 4

#if defined(__CUDA_ARCH_FEAT_SM103_ALL) || defined(__CUDA_ARCH_FEAT_SM100_ALL) || defined(__CUDA_ARCH_FEAT_SM101_ALL)
#define HAS_TCGEN05 1
#else
#define HAS_TCGEN05 0
#endif

// cg2 GEMM: cluster tile 256x512, K=64 floats per stage (2 SW128 atom blocks)
#define NST  2
#define C2_A_BYTES 32768                  // 128 rows x 2 kblocks x 128B
#define C2_B_BYTES 65536                  // 256 rows x 2 kblocks x 128B
#define C2_STAGE   (C2_A_BYTES + C2_B_BYTES)   // 96 KB
#define C2_SMEM    (NST * C2_STAGE + 1024)     // 193 KB

// ---------------- scratch (static device globals; no allocations) ----------
__device__ float g_p   [(size_t)NROWS * NPROJ];   // packed skip|q|k|v
__device__ float g_vt  [(size_t)DDIM * NROWS];
__device__ float g_ap  [(size_t)KSPLIT_AV * NROWS * DDIM];  // AV split-K partials
__device__ float g_h   [(size_t)NROWS * DDIM];
__device__ float g_s   [(size_t)NROWS * NROWS];   // 268 MB exp(scores)
__device__ float g_rx  [(size_t)NROWS * DDIM];
__device__ float g_wcT [(size_t)NPROJ * DDIM];
__device__ float g_wfT [(size_t)DDIM * DDIM];
__device__ float g_bc  [NPROJ];
__device__ float g_part[(size_t)NROWS * QKTILES];
__device__ float g_inv [NROWS];
__device__ float g_u   [DDIM];
__device__ float g_w   [DDIM];

// ---------------- generic helpers -------------------------------------------
__device__ __forceinline__ float rna_tf32(float x) {
    uint32_t u;
    asm("cvt.rna.tf32.f32 %0, %1;" : "=r"(u) : "f"(x));
    return __uint_as_float(u);
}
__device__ __forceinline__ void cp16(uint32_t s, const void* g) {
    asm volatile("cp.async.cg.shared.global [%0], [%1], 16;\n" :: "r"(s), "l"(g));
}
__device__ __forceinline__ void cp_commit() { asm volatile("cp.async.commit_group;\n"); }
template<int Ng> __device__ __forceinline__ void cp_waitg() {
    asm volatile("cp.async.wait_group %0;\n" :: "n"(Ng));
}
__device__ __forceinline__ uint32_t sw128(uint32_t off) { return off ^ ((off >> 3) & 0x70); }
__device__ __forceinline__ uint32_t s2u(const void* p) {
    return (uint32_t)__cvta_generic_to_shared(p);
}

// ---------------- tcgen05/cluster helpers (guarded) --------------------------
__device__ __forceinline__ bool elect1() {
#if HAS_TCGEN05
    uint32_t p;
    asm volatile("{\n\t.reg .pred P;\n\telect.sync _|P, 0xFFFFFFFF;\n\t"
                 "selp.b32 %0, 1, 0, P;\n\t}" : "=r"(p));
    return p != 0;
#else
    return false;
#endif
}
__device__ __forceinline__ void mbar_init(uint32_t a, uint32_t c) {
    asm volatile("mbarrier.init.shared.b64 [%0], %1;" :: "r"(a), "r"(c) : "memory");
}
__device__ __forceinline__ void mbar_wait(uint32_t a, uint32_t parity) {
    asm volatile(
        "{\n\t.reg .pred P;\n\t"
        "W_%=:\n\t"
        "mbarrier.try_wait.parity.acquire.cta.shared::cta.b64 P, [%0], %1, 0x989680;\n\t"
        "@P bra.uni D_%=;\n\t"
        "bra.uni W_%=;\n\t"
        "D_%=:\n\t}"
        :: "r"(a), "r"(parity) : "memory");
}
__device__ __forceinline__ void mbar_wait_cluster(uint32_t a, uint32_t parity) {
#if HAS_TCGEN05
    asm volatile(
        "{\n\t.reg .pred P;\n\t"
        "W_%=:\n\t"
        "mbarrier.try_wait.parity.acquire.cluster.shared::cta.b64 P, [%0], %1, 0x989680;\n\t"
        "@P bra.uni D_%=;\n\t"
        "bra.uni W_%=;\n\t"
        "D_%=:\n\t}"
        :: "r"(a), "r"(parity) : "memory");
#endif
}
__device__ __forceinline__ void arrive_rank0(uint32_t local_addr) {
#if HAS_TCGEN05
    asm volatile(
        "{\n\t.reg .b32 ra;\n\t"
        "mapa.shared::cluster.u32 ra, %0, 0;\n\t"
        "mbarrier.arrive.shared::cluster.b64 _, [ra];\n\t}"
        :: "r"(local_addr) : "memory");
#endif
}
__device__ __forceinline__ void cluster_sync() {
#if HAS_TCGEN05
    asm volatile("barrier.cluster.arrive.aligned;" ::: "memory");
    asm volatile("barrier.cluster.wait.aligned;" ::: "memory");
#endif
}
__device__ __forceinline__ uint64_t sdesc(uint32_t addr) {
    return ((uint64_t)2 << 61) | ((uint64_t)1 << 46) | ((uint64_t)64 << 32)
         | ((uint64_t)1 << 16) | ((addr >> 4) & 0x3FFF);
}
__device__ __forceinline__ void mma_tf32_cg2(uint32_t d, uint64_t ad, uint64_t bd,
                                             uint32_t idesc, uint32_t en) {
#if HAS_TCGEN05
    asm volatile(
        "{\n\t.reg .pred p;\n\tsetp.ne.u32 p, %4, 0;\n\t"
        "tcgen05.mma.cta_group::2.kind::tf32 [%0], %1, %2, %3, "
        "{%5,%5,%5,%5,%5,%5,%5,%5}, p;\n\t}"
        :: "r"(d), "l"(ad), "l"(bd), "r"(idesc), "r"(en), "r"(0u) : "memory");
#endif
}
__device__ __forceinline__ void commit_mc2(uint32_t mbar) {
#if HAS_TCGEN05
    asm volatile(
        "tcgen05.commit.cta_group::2.mbarrier::arrive::one.shared::cluster"
        ".multicast::cluster.b64 [%0], %1;"
        :: "r"(mbar), "h"((uint16_t)0x3) : "memory");
#endif
}
__device__ __forceinline__ void ldtm32(uint32_t* r, uint32_t addr) {
#if HAS_TCGEN05
    asm volatile(
        "tcgen05.ld.sync.aligned.32x32b.x32.b32 "
        "{%0,%1,%2,%3,%4,%5,%6,%7,%8,%9,%10,%11,%12,%13,%14,%15,"
        "%16,%17,%18,%19,%20,%21,%22,%23,%24,%25,%26,%27,%28,%29,%30,%31}, [%32];"
        : "=r"(r[0]),  "=r"(r[1]),  "=r"(r[2]),  "=r"(r[3]),
          "=r"(r[4]),  "=r"(r[5]),  "=r"(r[6]),  "=r"(r[7]),
          "=r"(r[8]),  "=r"(r[9]),  "=r"(r[10]), "=r"(r[11]),
          "=r"(r[12]), "=r"(r[13]), "=r"(r[14]), "=r"(r[15]),
          "=r"(r[16]), "=r"(r[17]), "=r"(r[18]), "=r"(r[19]),
          "=r"(r[20]), "=r"(r[21]), "=r"(r[22]), "=r"(r[23]),
          "=r"(r[24]), "=r"(r[25]), "=r"(r[26]), "=r"(r[27]),
          "=r"(r[28]), "=r"(r[29]), "=r"(r[30]), "=r"(r[31])
        : "r"(addr));
#endif
}

// ---------------- cg2 tcgen05 TF32 GEMM (NT), 256x512, K=64/stage ------------
// C = alpha*(A[M,Ktot] @ B[N,Ktot]^T), K per launch-chunk = K param.
// blockIdx.x encodes (rank, ntile, kchunk): cx=bx>>1; ntile=cx%ntiles; kc=cx/ntiles.
// MODE: 0 +bias | 1 +bias,tf32 out | 2 exp->tf32 + row partials | 4 raw store
template<int MODE>
__global__ __launch_bounds__(256, 1) __cluster_dims__(2, 1, 1)
void gemm_cg2(const float* __restrict__ A, int lda,
              const float* __restrict__ B, int ldb,
              const float* __restrict__ bias,
              float* __restrict__ C, int ldc, int K, int Nstore, float alpha,
              int ntiles, size_t cChunkStride)
{
#if HAS_TCGEN05
    extern __shared__ char dsm[];
    __shared__ uint32_t s_tmem;
    __shared__ __align__(8) uint64_t s_full[NST];
    __shared__ __align__(8) uint64_t s_done[NST];
    __shared__ float sred[2][128];

    const int tid  = threadIdx.x;
    const int lane = tid & 31;
    const int wid  = tid >> 5;
    uint32_t rank;
    asm("mov.u32 %0, %%cluster_ctarank;" : "=r"(rank));

    const int cx    = blockIdx.x >> 1;
    const int ntile = cx % ntiles;
    const int kc    = cx / ntiles;
    const int col0  = ntile * NTILE;
    const int row0  = blockIdx.y * 256;
    const int aRow0 = row0 + (int)rank * 128;

    A += (size_t)kc * K;
    B += (size_t)kc * K;
    C += (size_t)kc * cChunkStride;

    const uint32_t base = (s2u(dsm) + 1023u) & ~1023u;

    if (tid == 0) {
#pragma unroll
        for (int i = 0; i < NST; i++) {
            mbar_init(s2u(&s_full[i]), 2);
            mbar_init(s2u(&s_done[i]), 1);
        }
    }
    if (wid == 0) {
        asm volatile("tcgen05.alloc.cta_group::2.sync.aligned.shared::cta.b32 [%0], %1;"
                     :: "r"(s2u(&s_tmem)), "r"(512u) : "memory");
    }
    __syncthreads();
    cluster_sync();
    const uint32_t tmem = s_tmem;

    const uint32_t idesc = (1u << 4) | (2u << 7) | (2u << 10)
                         | ((256 / 8) << 17) | ((256 / 16) << 24);

    const int stages = K / 64;

    auto load_stage = [&](int s) {
        const int buf = s & 1;
        const int k0  = s * 64;
        const uint32_t ab = base + buf * C2_STAGE;
        const uint32_t bb = ab + C2_A_BYTES;
        // A: 128 rows x 2 kblocks x 128B  (2048 chunks)
#pragma unroll
        for (int it = 0; it < 8; it++) {
            int idx = tid + it * 256;
            int blk = idx >> 10, rem = idx & 1023;
            int r = rem >> 3, cb = rem & 7;
            cp16(ab + blk * 16384 + sw128(r * 128 + cb * 16),
                 A + (size_t)(aRow0 + r) * lda + k0 + blk * 32 + cb * 4);
        }
        // B: 256 local rows x 2 kblocks x 128B  (4096 chunks)
#pragma unroll
        for (int it = 0; it < 16; it++) {
            int idx = tid + it * 256;
            int blk = idx >> 11, rem = idx & 2047;
            int j = rem >> 3, cb = rem & 7;
            int g = col0 + ((j >> 7) << 8) + (int)rank * 128 + (j & 127);
            cp16(bb + blk * 32768 + sw128(j * 128 + cb * 16),
                 B + (size_t)g * ldb + k0 + blk * 32 + cb * 4);
        }
        cp_commit();
    };

    load_stage(0);
    if (stages > 1) load_stage(1);

    for (int s = 0; s < stages; s++) {
        if (s + 1 < stages) cp_waitg<1>();
        else                cp_waitg<0>();
        __syncthreads();

        if (tid == 0) {
            asm volatile("fence.proxy.async.shared::cta;" ::: "memory");
            arrive_rank0(s2u(&s_full[s & 1]));
        }

        if (rank == 0 && wid == 0) {
            if (elect1()) {
                mbar_wait_cluster(s2u(&s_full[s & 1]), (uint32_t)((s >> 1) & 1));
                const uint32_t ab = base + (s & 1) * C2_STAGE;
                const uint64_t ad = sdesc(ab);
                const uint64_t bd = sdesc(ab + C2_A_BYTES);
#pragma unroll
                for (int ks = 0; ks < 8; ks++) {
                    uint32_t en = (s > 0 || ks > 0) ? 1u : 0u;
                    uint64_t ao = (uint64_t)((ks >> 2) * 1024 + (ks & 3) * 2);
                    uint64_t bo = (uint64_t)((ks >> 2) * 2048 + (ks & 3) * 2);
                    mma_tf32_cg2(tmem,       ad + ao, bd + bo,        idesc, en);
                    mma_tf32_cg2(tmem + 256, ad + ao, bd + bo + 1024, idesc, en);
                }
                commit_mc2(s2u(&s_done[s & 1]));
            }
        }

        const int t = s + 2;
        if (t < stages) {
            // buffer t&1 == s&1: wait for MMA(s) completion before overwrite
            mbar_wait(s2u(&s_done[s & 1]), (uint32_t)((s >> 1) & 1));
            load_stage(t);
        }
    }

    mbar_wait(s2u(&s_done[(stages - 1) & 1]),
              (uint32_t)(((stages - 1) >> 1) & 1));
    asm volatile("tcgen05.fence::after_thread_sync;" ::: "memory");

    // epilogue: this CTA's 128 rows x 512 cols
    {
        const int sub = wid & 3;
        const int half = wid >> 2;
        const int colBase = half * 256;
        const int r = aRow0 + sub * 32 + lane;
        float rowsum = 0.f;
        uint32_t d[32];
#pragma unroll
        for (int cb = 0; cb < 8; cb++) {
            ldtm32(d, tmem + colBase + cb * 32);
            asm volatile("tcgen05.wait::ld.sync.aligned;" ::: "memory");
            const int c0 = col0 + colBase + cb * 32;
            float* cp = C + (size_t)r * ldc + c0;
            if (c0 + 31 < Nstore) {
#pragma unroll
                for (int j = 0; j < 32; j += 4) {
                    float4 v;
                    v.x = alpha * __uint_as_float(d[j + 0]);
                    v.y = alpha * __uint_as_float(d[j + 1]);
                    v.z = alpha * __uint_as_float(d[j + 2]);
                    v.w = alpha * __uint_as_float(d[j + 3]);
                    if (MODE == 0 || MODE == 1) {
                        v.x += bias[c0 + j + 0]; v.y += bias[c0 + j + 1];
                        v.z += bias[c0 + j + 2]; v.w += bias[c0 + j + 3];
                    }
                    if (MODE == 2) {
                        v.x = rna_tf32(__expf(v.x)); v.y = rna_tf32(__expf(v.y));
                        v.z = rna_tf32(__expf(v.z)); v.w = rna_tf32(__expf(v.w));
                        rowsum += v.x + v.y + v.z + v.w;
                    }
                    if (MODE == 1) {
                        v.x = rna_tf32(v.x); v.y = rna_tf32(v.y);
                        v.z = rna_tf32(v.z); v.w = rna_tf32(v.w);
                    }
                    *(float4*)(cp + j) = v;
                }
            } else {
#pragma unroll
                for (int j = 0; j < 32; j++) {
                    if (c0 + j < Nstore) {
                        float v = alpha * __uint_as_float(d[j]);
                        if (MODE == 0 || MODE == 1) v += bias[c0 + j];
                        if (MODE == 2) { v = rna_tf32(__expf(v)); rowsum += v; }
                        if (MODE == 1) v = rna_tf32(v);
                        cp[j] = v;
                    }
                }
            }
        }
        asm volatile("tcgen05.fence::before_thread_sync;" ::: "memory");

        if (MODE == 2) {
            sred[half][sub * 32 + lane] = rowsum;
            __syncthreads();
            if (tid < 128) {
                float tot = sred[0][tid] + sred[1][tid];
                g_part[(size_t)(aRow0 + tid) * QKTILES + ntile] = tot;
            }
        }
    }

    __syncthreads();
    if (wid == 0) {
        asm volatile("tcgen05.relinquish_alloc_permit.cta_group::2.sync.aligned;");
        asm volatile("tcgen05.dealloc.cta_group::2.sync.aligned.b32 %0, %1;"
                     :: "r"(tmem), "r"(512u));
    }
    cluster_sync();
#endif  // HAS_TCGEN05
}

// ---------------- invert row sums -------------------------------------------
__global__ void invert_sums()
{
    int r = blockIdx.x * 256 + threadIdx.x;
    if (r < NROWS) {
        float s = 0.f;
#pragma unroll
        for (int t = 0; t < QKTILES; t++) s += g_part[(size_t)r * QKTILES + t];
        g_inv[r] = 1.f / s;
    }
}

// ---------------- transpose helpers ------------------------------------------
__device__ __forceinline__ void transpose_tile(
    const float* in, int in_ld, float* out, int R, int C, int outR,
    int bx, int by)
{
    __shared__ float t[32][33];
    const int x = threadIdx.x & 31;
    const int y = threadIdx.x >> 5;
#pragma unroll
    for (int dy = 0; dy < 4; dy++) {
        int r = by + y + dy * 8, c = bx + x;
        t[y + dy * 8][x] = (c < C) ? in[(size_t)r * in_ld + c] : 0.f;
    }
    __syncthreads();
#pragma unroll
    for (int dy = 0; dy < 4; dy++) {
        int c = bx + y + dy * 8, r = by + x;
        if (c < outR) out[(size_t)c * R + r] = rna_tf32(t[x][y + dy * 8]);
    }
}

// All 5 weight transposes in one launch: grid (32, 32, 5)
__global__ __launch_bounds__(256) void transpose_weights(
    const float* __restrict__ Ws, const float* __restrict__ Wq,
    const float* __restrict__ Wk, const float* __restrict__ Wv,
    const float* __restrict__ Wf)
{
    const int sec = blockIdx.z;
    const int bx = blockIdx.x * 32, by = blockIdx.y * 32;
    if (sec < 4) {
        const float* in = (sec == 0) ? Ws : (sec == 1) ? Wq : (sec == 2) ? Wk : Wv;
        transpose_tile(in, DDIM, g_wcT + (size_t)sec * DDIM * DDIM,
                       DDIM, DDIM, DDIM, bx, by);
    } else {
        transpose_tile(Wf, CDIM, g_wfT, DDIM, CDIM, DDIM, bx, by);
    }
}

// v^T from packed p (strided): grid (DDIM/32, NROWS/32)
__global__ __launch_bounds__(256) void transpose_v(const float* __restrict__ pv)
{
    transpose_tile(pv, NPROJ, g_vt, NROWS, DDIM, DDIM,
                   blockIdx.x * 32, blockIdx.y * 32);
}

// ---------------- small prep: round x + biases + beta fold -------------------
__global__ void round_copy(const float* __restrict__ s, float* __restrict__ d, int n)
{
    int i = (blockIdx.x * 256 + threadIdx.x) * 4;
    if (i < n) {
        float4 v = *(const float4*)(s + i);
        v.x = rna_tf32(v.x); v.y = rna_tf32(v.y);
        v.z = rna_tf32(v.z); v.w = rna_tf32(v.w);
        *(float4*)(d + i) = v;
    }
}
__global__ void prep_small(const float* __restrict__ bs, const float* __restrict__ bq,
                           const float* __restrict__ bk, const float* __restrict__ bv,
                           const float* __restrict__ Wb)
{
    int i = blockIdx.x * 256 + threadIdx.x;
    if (i < NPROJ) {
        int sec = i >> 10, c = i & 1023;
        g_bc[i] = (sec == 0) ? bs[c] : (sec == 1) ? bq[c] : (sec == 2) ? bk[c] : bv[c];
    }
    if (i < DDIM) {
        g_u[i] = Wb[i] + Wb[2 * DDIM + i];
        g_w[i] = Wb[DDIM + i] - Wb[2 * DDIM + i];
    }
}

// ---------------- fused split-K combine + beta + gate ------------------------
// a = inv[row] * sum_k partial_k;  h = beta*x_r + (1-beta)*a  (tf32 out)
__global__ __launch_bounds__(256) void beta_gate(
    const float* __restrict__ ap, const float* __restrict__ xr, int xld,
    const float* __restrict__ b_beta, float* __restrict__ h)
{
    __shared__ float sa[DDIM];
    __shared__ float sx[DDIM];
    __shared__ float red[256];
    const int row = blockIdx.x;
    const int tid = threadIdx.x;
    const float* px = xr + (size_t)row * xld;
    const float inv = g_inv[row];
    const size_t chunk = (size_t)NROWS * DDIM;
    const float* p0 = ap + (size_t)row * DDIM;

    float part = 0.f;
    for (int i = tid; i < DDIM; i += 256) {
        float av = inv * (p0[i] + p0[chunk + i] + p0[2 * chunk + i] + p0[3 * chunk + i]);
        float xv = px[i];
        sa[i] = av; sx[i] = xv;
        part += av * g_u[i] + xv * g_w[i];
    }
    red[tid] = part; __syncthreads();
    for (int s = 128; s > 0; s >>= 1) {
        if (tid < s) red[tid] += red[tid + s];
        __syncthreads();
    }
    float z = red[0] + b_beta[0];
    float beta = 1.f / (1.f + __expf(-z));

    float* ph = h + (size_t)row * DDIM;
    for (int i = tid; i < DDIM; i += 256)
        ph[i] = rna_tf32(beta * sx[i] + (1.f - beta) * sa[i]);
}

// ---------------------------------------------------------------------------
extern "C" void kernel_launch(void* const* d_in, const int* in_sizes, int n_in,
                              void* d_out, int out_size)
{
    const float* x      = (const float*)d_in[0];
    const float* W_skip = (const float*)d_in[1];
    const float* b_skip = (const float*)d_in[2];
    const float* W_q    = (const float*)d_in[3];
    const float* b_q    = (const float*)d_in[4];
    const float* W_k    = (const float*)d_in[5];
    const float* b_k    = (const float*)d_in[6];
    const float* W_v    = (const float*)d_in[7];
    const float* b_v    = (const float*)d_in[8];
    const float* W_beta = (const float*)d_in[9];
    const float* b_beta = (const float*)d_in[10];
    const float* W_fc   = (const float*)d_in[11];
    const float* b_fc   = (const float*)d_in[12];
    float* out = (float*)d_out;

    float *p, *vt, *ap, *h, *s, *rx, *wcT, *wfT, *bc;
    cudaGetSymbolAddress((void**)&p,   g_p);
    cudaGetSymbolAddress((void**)&vt,  g_vt);
    cudaGetSymbolAddress((void**)&ap,  g_ap);
    cudaGetSymbolAddress((void**)&h,   g_h);
    cudaGetSymbolAddress((void**)&s,   g_s);
    cudaGetSymbolAddress((void**)&rx,  g_rx);
    cudaGetSymbolAddress((void**)&wcT, g_wcT);
    cudaGetSymbolAddress((void**)&wfT, g_wfT);
    cudaGetSymbolAddress((void**)&bc,  g_bc);

    cudaFuncSetAttribute((const void*)gemm_cg2<0>,
                         cudaFuncAttributeMaxDynamicSharedMemorySize, C2_SMEM);
    cudaFuncSetAttribute((const void*)gemm_cg2<1>,
                         cudaFuncAttributeMaxDynamicSharedMemorySize, C2_SMEM);
    cudaFuncSetAttribute((const void*)gemm_cg2<2>,
                         cudaFuncAttributeMaxDynamicSharedMemorySize, C2_SMEM);
    cudaFuncSetAttribute((const void*)gemm_cg2<4>,
                         cudaFuncAttributeMaxDynamicSharedMemorySize, C2_SMEM);

    const int nd = NROWS * DDIM;

    // 0: round x
    round_copy<<<(nd / 4 + 255) / 256, 256>>>(x, rx, nd);
    // 1: all weight transposes
    transpose_weights<<<dim3(32, 32, 5), 256>>>(W_skip, W_q, W_k, W_v, W_fc);
    // 2: biases + beta fold
    prep_small<<<NPROJ / 256, 256>>>(b_skip, b_q, b_k, b_v, W_beta);

    // 3: fused projections: p = rx @ wcT^T + bc (tf32-rounded)
    {
        dim3 g(2 * (NPROJ / NTILE), NROWS / 256);
        gemm_cg2<1><<<g, 256, C2_SMEM>>>(rx, DDIM, wcT, DDIM, bc,
                                         p, NPROJ, DDIM, NPROJ, 1.f,
                                         NPROJ / NTILE, 0);
    }
    // 4: v^T
    transpose_v<<<dim3(DDIM / 32, NROWS / 32), 256>>>(p + 3 * DDIM);

    // 5: S = exp(q @ k^T / 32), tf32; per-tile row sums   (ncu -s 5 target)
    {
        dim3 g(2 * (NROWS / NTILE), NROWS / 256);
        gemm_cg2<2><<<g, 256, C2_SMEM>>>(p + 1 * DDIM, NPROJ, p + 2 * DDIM, NPROJ,
                                         nullptr, s, NROWS, DDIM, NROWS, 0.03125f,
                                         NROWS / NTILE, 0);
    }
    // 6: 1/rowsum
    invert_sums<<<NROWS / 256, 256>>>();

    // 7: AV split-K=4: partial_k = S[:, kc] @ vt[:, kc]^T
    {
        dim3 g(2 * (DDIM / NTILE) * KSPLIT_AV, NROWS / 256);
        gemm_cg2<4><<<g, 256, C2_SMEM>>>(s, NROWS, vt, NROWS, nullptr,
                                         ap, DDIM, NROWS / KSPLIT_AV, DDIM, 1.f,
                                         DDIM / NTILE, (size_t)NROWS * DDIM);
    }
    // 8: combine + beta + gate
    beta_gate<<<NROWS, 256>>>(ap, p, NPROJ, b_beta, h);

    // 9: out = h @ W_fc + b_fc
    {
        dim3 g(2 * (DDIM / NTILE), NROWS / 256);
        gemm_cg2<0><<<g, 256, C2_SMEM>>>(h, DDIM, wfT, DDIM, b_fc,
                                         out, CDIM, DDIM, CDIM, 1.f,
                                         DDIM / NTILE, 0);
    }
}

// round 12
// speedup vs baseline: 1.2464x; 1.2464x over previous
#include <cuda_runtime.h>
#include <cstdint>
#include <cstddef>

#define NROWS 8192
#define DDIM  1024
#define CDIM  1000
#define NPROJ 4096   // skip|q|k|v packed
#define NTILE 512    // cluster N-tile
#define QKTILES (NROWS / NTILE)   // 16 col-tiles in QK
#define KSPLIT_AV 4

#if defined(__CUDA_ARCH_FEAT_SM103_ALL) || defined(__CUDA_ARCH_FEAT_SM100_ALL) || defined(__CUDA_ARCH_FEAT_SM101_ALL)
#define HAS_TCGEN05 1
#else
#define HAS_TCGEN05 0
#endif

// cg2 GEMM: cluster tile 256x512, K=32 floats per stage, 4-deep ring
#define NST  4
#define C2_A_BYTES 16384                  // 128 rows x 128B
#define C2_B_BYTES 32768                  // 256 rows x 128B
#define C2_STAGE   (C2_A_BYTES + C2_B_BYTES)   // 48 KB
#define C2_SMEM    (NST * C2_STAGE + 1024)     // 193 KB

// ---------------- scratch (static device globals; no allocations) ----------
__device__ float g_p   [(size_t)NROWS * NPROJ];   // packed skip|q|k|v
__device__ float g_vt  [(size_t)DDIM * NROWS];
__device__ float g_ap  [(size_t)KSPLIT_AV * NROWS * DDIM];  // AV split-K partials
__device__ float g_h   [(size_t)NROWS * DDIM];
__device__ float g_s   [(size_t)NROWS * NROWS];   // 268 MB exp(scores)
__device__ float g_rx  [(size_t)NROWS * DDIM];
__device__ float g_wcT [(size_t)NPROJ * DDIM];
__device__ float g_wfT [(size_t)DDIM * DDIM];
__device__ float g_bc  [NPROJ];
__device__ float g_part[(size_t)NROWS * QKTILES];
__device__ float g_inv [NROWS];
__device__ float g_u   [DDIM];
__device__ float g_w   [DDIM];

// ---------------- generic helpers -------------------------------------------
__device__ __forceinline__ float rna_tf32(float x) {
    uint32_t u;
    asm("cvt.rna.tf32.f32 %0, %1;" : "=r"(u) : "f"(x));
    return __uint_as_float(u);
}
__device__ __forceinline__ void cp16(uint32_t s, const void* g) {
    asm volatile("cp.async.cg.shared.global [%0], [%1], 16;\n" :: "r"(s), "l"(g));
}
__device__ __forceinline__ void cp_commit() { asm volatile("cp.async.commit_group;\n"); }
template<int Ng> __device__ __forceinline__ void cp_waitg() {
    asm volatile("cp.async.wait_group %0;\n" :: "n"(Ng));
}
__device__ __forceinline__ uint32_t sw128(uint32_t off) { return off ^ ((off >> 3) & 0x70); }
__device__ __forceinline__ uint32_t s2u(const void* p) {
    return (uint32_t)__cvta_generic_to_shared(p);
}

// ---------------- tcgen05/cluster helpers (guarded) --------------------------
__device__ __forceinline__ bool elect1() {
#if HAS_TCGEN05
    uint32_t p;
    asm volatile("{\n\t.reg .pred P;\n\telect.sync _|P, 0xFFFFFFFF;\n\t"
                 "selp.b32 %0, 1, 0, P;\n\t}" : "=r"(p));
    return p != 0;
#else
    return false;
#endif
}
__device__ __forceinline__ void mbar_init(uint32_t a, uint32_t c) {
    asm volatile("mbarrier.init.shared.b64 [%0], %1;" :: "r"(a), "r"(c) : "memory");
}
__device__ __forceinline__ void mbar_wait(uint32_t a, uint32_t parity) {
    asm volatile(
        "{\n\t.reg .pred P;\n\t"
        "W_%=:\n\t"
        "mbarrier.try_wait.parity.acquire.cta.shared::cta.b64 P, [%0], %1, 0x989680;\n\t"
        "@P bra.uni D_%=;\n\t"
        "bra.uni W_%=;\n\t"
        "D_%=:\n\t}"
        :: "r"(a), "r"(parity) : "memory");
}
__device__ __forceinline__ void mbar_wait_cluster(uint32_t a, uint32_t parity) {
#if HAS_TCGEN05
    asm volatile(
        "{\n\t.reg .pred P;\n\t"
        "W_%=:\n\t"
        "mbarrier.try_wait.parity.acquire.cluster.shared::cta.b64 P, [%0], %1, 0x989680;\n\t"
        "@P bra.uni D_%=;\n\t"
        "bra.uni W_%=;\n\t"
        "D_%=:\n\t}"
        :: "r"(a), "r"(parity) : "memory");
#endif
}
__device__ __forceinline__ void arrive_rank0(uint32_t local_addr) {
#if HAS_TCGEN05
    asm volatile(
        "{\n\t.reg .b32 ra;\n\t"
        "mapa.shared::cluster.u32 ra, %0, 0;\n\t"
        "mbarrier.arrive.shared::cluster.b64 _, [ra];\n\t}"
        :: "r"(local_addr) : "memory");
#endif
}
__device__ __forceinline__ void cluster_sync() {
#if HAS_TCGEN05
    asm volatile("barrier.cluster.arrive.aligned;" ::: "memory");
    asm volatile("barrier.cluster.wait.aligned;" ::: "memory");
#endif
}
__device__ __forceinline__ uint64_t sdesc(uint32_t addr) {
    return ((uint64_t)2 << 61) | ((uint64_t)1 << 46) | ((uint64_t)64 << 32)
         | ((uint64_t)1 << 16) | ((addr >> 4) & 0x3FFF);
}
__device__ __forceinline__ void mma_tf32_cg2(uint32_t d, uint64_t ad, uint64_t bd,
                                             uint32_t idesc, uint32_t en) {
#if HAS_TCGEN05
    asm volatile(
        "{\n\t.reg .pred p;\n\tsetp.ne.u32 p, %4, 0;\n\t"
        "tcgen05.mma.cta_group::2.kind::tf32 [%0], %1, %2, %3, "
        "{%5,%5,%5,%5,%5,%5,%5,%5}, p;\n\t}"
        :: "r"(d), "l"(ad), "l"(bd), "r"(idesc), "r"(en), "r"(0u) : "memory");
#endif
}
__device__ __forceinline__ void commit_mc2(uint32_t mbar) {
#if HAS_TCGEN05
    asm volatile(
        "tcgen05.commit.cta_group::2.mbarrier::arrive::one.shared::cluster"
        ".multicast::cluster.b64 [%0], %1;"
        :: "r"(mbar), "h"((uint16_t)0x3) : "memory");
#endif
}
__device__ __forceinline__ void ldtm32(uint32_t* r, uint32_t addr) {
#if HAS_TCGEN05
    asm volatile(
        "tcgen05.ld.sync.aligned.32x32b.x32.b32 "
        "{%0,%1,%2,%3,%4,%5,%6,%7,%8,%9,%10,%11,%12,%13,%14,%15,"
        "%16,%17,%18,%19,%20,%21,%22,%23,%24,%25,%26,%27,%28,%29,%30,%31}, [%32];"
        : "=r"(r[0]),  "=r"(r[1]),  "=r"(r[2]),  "=r"(r[3]),
          "=r"(r[4]),  "=r"(r[5]),  "=r"(r[6]),  "=r"(r[7]),
          "=r"(r[8]),  "=r"(r[9]),  "=r"(r[10]), "=r"(r[11]),
          "=r"(r[12]), "=r"(r[13]), "=r"(r[14]), "=r"(r[15]),
          "=r"(r[16]), "=r"(r[17]), "=r"(r[18]), "=r"(r[19]),
          "=r"(r[20]), "=r"(r[21]), "=r"(r[22]), "=r"(r[23]),
          "=r"(r[24]), "=r"(r[25]), "=r"(r[26]), "=r"(r[27]),
          "=r"(r[28]), "=r"(r[29]), "=r"(r[30]), "=r"(r[31])
        : "r"(addr));
#endif
}

// ---------------- cg2 tcgen05 TF32 GEMM (NT), 256x512, K=32/stage, 4 ring ----
// C = alpha*(A[M,Ktot] @ B[N,Ktot]^T), K per launch-chunk = K param.
// blockIdx.x encodes (rank, ntile, kchunk): cx=bx>>1; ntile=cx%ntiles; kc=cx/ntiles.
// MODE: 0 +bias | 1 +bias,tf32 out | 2 exp->tf32 + row partials | 4 raw store
template<int MODE>
__global__ __launch_bounds__(256, 1) __cluster_dims__(2, 1, 1)
void gemm_cg2(const float* __restrict__ A, int lda,
              const float* __restrict__ B, int ldb,
              const float* __restrict__ bias,
              float* __restrict__ C, int ldc, int K, int Nstore, float alpha,
              int ntiles, size_t cChunkStride)
{
#if HAS_TCGEN05
    extern __shared__ char dsm[];
    __shared__ uint32_t s_tmem;
    __shared__ __align__(8) uint64_t s_full[NST];
    __shared__ __align__(8) uint64_t s_done[NST];
    __shared__ float sred[2][128];

    const int tid  = threadIdx.x;
    const int lane = tid & 31;
    const int wid  = tid >> 5;
    uint32_t rank;
    asm("mov.u32 %0, %%cluster_ctarank;" : "=r"(rank));

    const int cx    = blockIdx.x >> 1;
    const int ntile = cx % ntiles;
    const int kc    = cx / ntiles;
    const int col0  = ntile * NTILE;
    const int row0  = blockIdx.y * 256;
    const int aRow0 = row0 + (int)rank * 128;

    A += (size_t)kc * K;
    B += (size_t)kc * K;
    C += (size_t)kc * cChunkStride;

    const uint32_t base = (s2u(dsm) + 1023u) & ~1023u;

    if (tid == 0) {
#pragma unroll
        for (int i = 0; i < NST; i++) {
            mbar_init(s2u(&s_full[i]), 2);
            mbar_init(s2u(&s_done[i]), 1);
        }
    }
    if (wid == 0) {
        asm volatile("tcgen05.alloc.cta_group::2.sync.aligned.shared::cta.b32 [%0], %1;"
                     :: "r"(s2u(&s_tmem)), "r"(512u) : "memory");
    }
    __syncthreads();
    cluster_sync();
    const uint32_t tmem = s_tmem;

    const uint32_t idesc = (1u << 4) | (2u << 7) | (2u << 10)
                         | ((256 / 8) << 17) | ((256 / 16) << 24);

    const int stages = K / 32;

    auto load_stage = [&](int s) {
        const int buf = s & (NST - 1);
        const int k0  = s * 32;
        const uint32_t ab = base + buf * C2_STAGE;
        const uint32_t bb = ab + C2_A_BYTES;
        // A: 128 rows x 128B (1024 chunks)
#pragma unroll
        for (int it = 0; it < 4; it++) {
            int idx = tid + it * 256;
            int r = idx >> 3, cb = idx & 7;
            cp16(ab + sw128(r * 128 + cb * 16),
                 A + (size_t)(aRow0 + r) * lda + k0 + cb * 4);
        }
        // B: 256 local rows x 128B (2048 chunks); halves serve the 2 N-MMAs
#pragma unroll
        for (int it = 0; it < 8; it++) {
            int idx = tid + it * 256;
            int j = idx >> 3, cb = idx & 7;
            int g = col0 + ((j >> 7) << 8) + (int)rank * 128 + (j & 127);
            cp16(bb + sw128(j * 128 + cb * 16),
                 B + (size_t)g * ldb + k0 + cb * 4);
        }
        cp_commit();
    };

    // prologue: 3-deep lookahead
    const int pro = (stages < NST - 1) ? stages : NST - 1;
    for (int p0 = 0; p0 < pro; p0++) load_stage(p0);

    for (int s = 0; s < stages; s++) {
        // wait until stage s's cp.async group retired
        if (stages - s >= 3)      cp_waitg<2>();
        else if (stages - s == 2) cp_waitg<1>();
        else                      cp_waitg<0>();
        __syncthreads();

        if (tid == 0) {
            asm volatile("fence.proxy.async.shared::cta;" ::: "memory");
            arrive_rank0(s2u(&s_full[s & (NST - 1)]));
        }

        if (rank == 0 && wid == 0) {
            if (elect1()) {
                mbar_wait_cluster(s2u(&s_full[s & (NST - 1)]),
                                  (uint32_t)((s >> 2) & 1));
                const uint32_t ab = base + (s & (NST - 1)) * C2_STAGE;
                const uint64_t ad = sdesc(ab);
                const uint64_t bd = sdesc(ab + C2_A_BYTES);
#pragma unroll
                for (int ks = 0; ks < 4; ks++) {
                    uint32_t en = (s > 0 || ks > 0) ? 1u : 0u;
                    mma_tf32_cg2(tmem,       ad + 2 * ks, bd + 2 * ks,        idesc, en);
                    mma_tf32_cg2(tmem + 256, ad + 2 * ks, bd + 2 * ks + 1024, idesc, en);
                }
                commit_mc2(s2u(&s_done[s & (NST - 1)]));
            }
        }

        const int t = s + NST - 1;
        if (t < stages) {
            // buffer t%NST == (s-1)%NST: wait MMA(s-1) completion before refill
            if (s >= 1) mbar_wait(s2u(&s_done[(s - 1) & (NST - 1)]),
                                  (uint32_t)(((s - 1) >> 2) & 1));
            load_stage(t);
        }
    }

    mbar_wait(s2u(&s_done[(stages - 1) & (NST - 1)]),
              (uint32_t)(((stages - 1) >> 2) & 1));
    asm volatile("tcgen05.fence::after_thread_sync;" ::: "memory");

    // epilogue: this CTA's 128 rows x 512 cols
    {
        const int sub = wid & 3;
        const int half = wid >> 2;
        const int colBase = half * 256;
        const int r = aRow0 + sub * 32 + lane;
        float rowsum = 0.f;
        uint32_t d[32];
#pragma unroll
        for (int cb = 0; cb < 8; cb++) {
            ldtm32(d, tmem + colBase + cb * 32);
            asm volatile("tcgen05.wait::ld.sync.aligned;" ::: "memory");
            const int c0 = col0 + colBase + cb * 32;
            float* cp = C + (size_t)r * ldc + c0;
            if (c0 + 31 < Nstore) {
#pragma unroll
                for (int j = 0; j < 32; j += 4) {
                    float4 v;
                    v.x = alpha * __uint_as_float(d[j + 0]);
                    v.y = alpha * __uint_as_float(d[j + 1]);
                    v.z = alpha * __uint_as_float(d[j + 2]);
                    v.w = alpha * __uint_as_float(d[j + 3]);
                    if (MODE == 0 || MODE == 1) {
                        v.x += bias[c0 + j + 0]; v.y += bias[c0 + j + 1];
                        v.z += bias[c0 + j + 2]; v.w += bias[c0 + j + 3];
                    }
                    if (MODE == 2) {
                        v.x = rna_tf32(__expf(v.x)); v.y = rna_tf32(__expf(v.y));
                        v.z = rna_tf32(__expf(v.z)); v.w = rna_tf32(__expf(v.w));
                        rowsum += v.x + v.y + v.z + v.w;
                    }
                    if (MODE == 1) {
                        v.x = rna_tf32(v.x); v.y = rna_tf32(v.y);
                        v.z = rna_tf32(v.z); v.w = rna_tf32(v.w);
                    }
                    *(float4*)(cp + j) = v;
                }
            } else {
#pragma unroll
                for (int j = 0; j < 32; j++) {
                    if (c0 + j < Nstore) {
                        float v = alpha * __uint_as_float(d[j]);
                        if (MODE == 0 || MODE == 1) v += bias[c0 + j];
                        if (MODE == 2) { v = rna_tf32(__expf(v)); rowsum += v; }
                        if (MODE == 1) v = rna_tf32(v);
                        cp[j] = v;
                    }
                }
            }
        }
        asm volatile("tcgen05.fence::before_thread_sync;" ::: "memory");

        if (MODE == 2) {
            sred[half][sub * 32 + lane] = rowsum;
            __syncthreads();
            if (tid < 128) {
                float tot = sred[0][tid] + sred[1][tid];
                g_part[(size_t)(aRow0 + tid) * QKTILES + ntile] = tot;
            }
        }
    }

    __syncthreads();
    if (wid == 0) {
        asm volatile("tcgen05.relinquish_alloc_permit.cta_group::2.sync.aligned;");
        asm volatile("tcgen05.dealloc.cta_group::2.sync.aligned.b32 %0, %1;"
                     :: "r"(tmem), "r"(512u));
    }
    cluster_sync();
#endif  // HAS_TCGEN05
}

// ---------------- invert row sums -------------------------------------------
__global__ void invert_sums()
{
    int r = blockIdx.x * 256 + threadIdx.x;
    if (r < NROWS) {
        float s = 0.f;
#pragma unroll
        for (int t = 0; t < QKTILES; t++) s += g_part[(size_t)r * QKTILES + t];
        g_inv[r] = 1.f / s;
    }
}

// ---------------- transpose helpers ------------------------------------------
__device__ __forceinline__ void transpose_tile(
    const float* in, int in_ld, float* out, int R, int C, int outR,
    int bx, int by)
{
    __shared__ float t[32][33];
    const int x = threadIdx.x & 31;
    const int y = threadIdx.x >> 5;
#pragma unroll
    for (int dy = 0; dy < 4; dy++) {
        int r = by + y + dy * 8, c = bx + x;
        t[y + dy * 8][x] = (c < C) ? in[(size_t)r * in_ld + c] : 0.f;
    }
    __syncthreads();
#pragma unroll
    for (int dy = 0; dy < 4; dy++) {
        int c = bx + y + dy * 8, r = by + x;
        if (c < outR) out[(size_t)c * R + r] = rna_tf32(t[x][y + dy * 8]);
    }
}

// All 5 weight transposes in one launch: grid (32, 32, 5)
__global__ __launch_bounds__(256) void transpose_weights(
    const float* __restrict__ Ws, const float* __restrict__ Wq,
    const float* __restrict__ Wk, const float* __restrict__ Wv,
    const float* __restrict__ Wf)
{
    const int sec = blockIdx.z;
    const int bx = blockIdx.x * 32, by = blockIdx.y * 32;
    if (sec < 4) {
        const float* in = (sec == 0) ? Ws : (sec == 1) ? Wq : (sec == 2) ? Wk : Wv;
        transpose_tile(in, DDIM, g_wcT + (size_t)sec * DDIM * DDIM,
                       DDIM, DDIM, DDIM, bx, by);
    } else {
        transpose_tile(Wf, CDIM, g_wfT, DDIM, CDIM, DDIM, bx, by);
    }
}

// v^T from packed p (strided): grid (DDIM/32, NROWS/32)
__global__ __launch_bounds__(256) void transpose_v(const float* __restrict__ pv)
{
    transpose_tile(pv, NPROJ, g_vt, NROWS, DDIM, DDIM,
                   blockIdx.x * 32, blockIdx.y * 32);
}

// ---------------- small prep: round x + biases + beta fold -------------------
__global__ void round_copy(const float* __restrict__ s, float* __restrict__ d, int n)
{
    int i = (blockIdx.x * 256 + threadIdx.x) * 4;
    if (i < n) {
        float4 v = *(const float4*)(s + i);
        v.x = rna_tf32(v.x); v.y = rna_tf32(v.y);
        v.z = rna_tf32(v.z); v.w = rna_tf32(v.w);
        *(float4*)(d + i) = v;
    }
}
__global__ void prep_small(const float* __restrict__ bs, const float* __restrict__ bq,
                           const float* __restrict__ bk, const float* __restrict__ bv,
                           const float* __restrict__ Wb)
{
    int i = blockIdx.x * 256 + threadIdx.x;
    if (i < NPROJ) {
        int sec = i >> 10, c = i & 1023;
        g_bc[i] = (sec == 0) ? bs[c] : (sec == 1) ? bq[c] : (sec == 2) ? bk[c] : bv[c];
    }
    if (i < DDIM) {
        g_u[i] = Wb[i] + Wb[2 * DDIM + i];
        g_w[i] = Wb[DDIM + i] - Wb[2 * DDIM + i];
    }
}

// ---------------- fused split-K combine + beta + gate ------------------------
__global__ __launch_bounds__(256) void beta_gate(
    const float* __restrict__ ap, const float* __restrict__ xr, int xld,
    const float* __restrict__ b_beta, float* __restrict__ h)
{
    __shared__ float sa[DDIM];
    __shared__ float sx[DDIM];
    __shared__ float red[256];
    const int row = blockIdx.x;
    const int tid = threadIdx.x;
    const float* px = xr + (size_t)row * xld;
    const float inv = g_inv[row];
    const size_t chunk = (size_t)NROWS * DDIM;
    const float* p0 = ap + (size_t)row * DDIM;

    float part = 0.f;
    for (int i = tid; i < DDIM; i += 256) {
        float av = inv * (p0[i] + p0[chunk + i] + p0[2 * chunk + i] + p0[3 * chunk + i]);
        float xv = px[i];
        sa[i] = av; sx[i] = xv;
        part += av * g_u[i] + xv * g_w[i];
    }
    red[tid] = part; __syncthreads();
    for (int s = 128; s > 0; s >>= 1) {
        if (tid < s) red[tid] += red[tid + s];
        __syncthreads();
    }
    float z = red[0] + b_beta[0];
    float beta = 1.f / (1.f + __expf(-z));

    float* ph = h + (size_t)row * DDIM;
    for (int i = tid; i < DDIM; i += 256)
        ph[i] = rna_tf32(beta * sx[i] + (1.f - beta) * sa[i]);
}

// ---------------------------------------------------------------------------
extern "C" void kernel_launch(void* const* d_in, const int* in_sizes, int n_in,
                              void* d_out, int out_size)
{
    const float* x      = (const float*)d_in[0];
    const float* W_skip = (const float*)d_in[1];
    const float* b_skip = (const float*)d_in[2];
    const float* W_q    = (const float*)d_in[3];
    const float* b_q    = (const float*)d_in[4];
    const float* W_k    = (const float*)d_in[5];
    const float* b_k    = (const float*)d_in[6];
    const float* W_v    = (const float*)d_in[7];
    const float* b_v    = (const float*)d_in[8];
    const float* W_beta = (const float*)d_in[9];
    const float* b_beta = (const float*)d_in[10];
    const float* W_fc   = (const float*)d_in[11];
    const float* b_fc   = (const float*)d_in[12];
    float* out = (float*)d_out;

    float *p, *vt, *ap, *h, *s, *rx, *wcT, *wfT, *bc;
    cudaGetSymbolAddress((void**)&p,   g_p);
    cudaGetSymbolAddress((void**)&vt,  g_vt);
    cudaGetSymbolAddress((void**)&ap,  g_ap);
    cudaGetSymbolAddress((void**)&h,   g_h);
    cudaGetSymbolAddress((void**)&s,   g_s);
    cudaGetSymbolAddress((void**)&rx,  g_rx);
    cudaGetSymbolAddress((void**)&wcT, g_wcT);
    cudaGetSymbolAddress((void**)&wfT, g_wfT);
    cudaGetSymbolAddress((void**)&bc,  g_bc);

    cudaFuncSetAttribute((const void*)gemm_cg2<0>,
                         cudaFuncAttributeMaxDynamicSharedMemorySize, C2_SMEM);
    cudaFuncSetAttribute((const void*)gemm_cg2<1>,
                         cudaFuncAttributeMaxDynamicSharedMemorySize, C2_SMEM);
    cudaFuncSetAttribute((const void*)gemm_cg2<2>,
                         cudaFuncAttributeMaxDynamicSharedMemorySize, C2_SMEM);
    cudaFuncSetAttribute((const void*)gemm_cg2<4>,
                         cudaFuncAttributeMaxDynamicSharedMemorySize, C2_SMEM);

    const int nd = NROWS * DDIM;

    // 0: round x
    round_copy<<<(nd / 4 + 255) / 256, 256>>>(x, rx, nd);
    // 1: all weight transposes
    transpose_weights<<<dim3(32, 32, 5), 256>>>(W_skip, W_q, W_k, W_v, W_fc);
    // 2: biases + beta fold
    prep_small<<<NPROJ / 256, 256>>>(b_skip, b_q, b_k, b_v, W_beta);

    // 3: fused projections: p = rx @ wcT^T + bc (tf32-rounded)
    {
        dim3 g(2 * (NPROJ / NTILE), NROWS / 256);
        gemm_cg2<1><<<g, 256, C2_SMEM>>>(rx, DDIM, wcT, DDIM, bc,
                                         p, NPROJ, DDIM, NPROJ, 1.f,
                                         NPROJ / NTILE, 0);
    }
    // 4: v^T
    transpose_v<<<dim3(DDIM / 32, NROWS / 32), 256>>>(p + 3 * DDIM);

    // 5: S = exp(q @ k^T / 32), tf32; per-tile row sums   (ncu -s 5 target)
    {
        dim3 g(2 * (NROWS / NTILE), NROWS / 256);
        gemm_cg2<2><<<g, 256, C2_SMEM>>>(p + 1 * DDIM, NPROJ, p + 2 * DDIM, NPROJ,
                                         nullptr, s, NROWS, DDIM, NROWS, 0.03125f,
                                         NROWS / NTILE, 0);
    }
    // 6: 1/rowsum
    invert_sums<<<NROWS / 256, 256>>>();

    // 7: AV split-K=4: partial_k = S[:, kc] @ vt[:, kc]^T
    {
        dim3 g(2 * (DDIM / NTILE) * KSPLIT_AV, NROWS / 256);
        gemm_cg2<4><<<g, 256, C2_SMEM>>>(s, NROWS, vt, NROWS, nullptr,
                                         ap, DDIM, NROWS / KSPLIT_AV, DDIM, 1.f,
                                         DDIM / NTILE, (size_t)NROWS * DDIM);
    }
    // 8: combine + beta + gate
    beta_gate<<<NROWS, 256>>>(ap, p, NPROJ, b_beta, h);

    // 9: out = h @ W_fc + b_fc
    {
        dim3 g(2 * (DDIM / NTILE), NROWS / 256);
        gemm_cg2<0><<<g, 256, C2_SMEM>>>(h, DDIM, wfT, DDIM, b_fc,
                                         out, CDIM, DDIM, CDIM, 1.f,
                                         DDIM / NTILE, 0);
    }
}